// round 7
// baseline (speedup 1.0000x reference)
#include <cuda_runtime.h>
#include <math.h>
#include <stdint.h>

#define BB 2
#define TT 2048
#define DD 2048
#define NHEADS 16
#define NKVH 8
#define HDIM 128

// Scratch (allocation-free rule: __device__ globals)
static __device__ float g_q[(size_t)BB * NHEADS * TT * HDIM];   // [b][n][t][h]
static __device__ float g_kv[(size_t)BB * 16 * TT * HDIM];      // [b][j][t][h], j<8=K, j>=8=V
static __device__ float g_enc[(size_t)BB * TT * NHEADS * HDIM]; // [b][t][n*128+h]
static __device__ float2 g_tab[(size_t)BB * TT * 64];           // rope cos/sin
static __device__ float g_wt[(size_t)4096 * 2048];              // [q;kv] weights^T fp32 temp
static __device__ float g_wot[(size_t)2048 * 2048];             // w_out^T fp32 temp
// int8 two-level quant planes + per-row scales
static __device__ char g_xq1[(size_t)4096 * 2048], g_xq2[(size_t)4096 * 2048];
static __device__ char g_wtq1[(size_t)4096 * 2048], g_wtq2[(size_t)4096 * 2048];
static __device__ char g_woq1[(size_t)2048 * 2048], g_woq2[(size_t)2048 * 2048];
static __device__ char g_eq1[(size_t)4096 * 2048], g_eq2[(size_t)4096 * 2048];
static __device__ float g_xs[4096], g_wts[4096], g_wos[2048], g_es[4096];

// ---------------------------------------------------------------------------
// helpers
// ---------------------------------------------------------------------------
__device__ __forceinline__ float tf32r(float x) {
    uint32_t u;
    asm("cvt.rna.tf32.f32 %0, %1;" : "=r"(u) : "f"(x));
    return __uint_as_float(u);
}
__device__ __forceinline__ uint32_t smem_u32(const void* p) {
    return (uint32_t)__cvta_generic_to_shared(p);
}
__device__ __forceinline__ void ldm4(uint32_t* r, uint32_t addr) {
    asm volatile("ldmatrix.sync.aligned.m8n8.x4.shared.b16 {%0,%1,%2,%3}, [%4];"
                 : "=r"(r[0]), "=r"(r[1]), "=r"(r[2]), "=r"(r[3]) : "r"(addr));
}
__device__ __forceinline__ void mma_tf32(float* d, const uint32_t* a, const uint32_t* b) {
    asm volatile(
        "mma.sync.aligned.m16n8k8.row.col.f32.tf32.tf32.f32 "
        "{%0,%1,%2,%3}, {%4,%5,%6,%7}, {%8,%9}, {%0,%1,%2,%3};"
        : "+f"(d[0]), "+f"(d[1]), "+f"(d[2]), "+f"(d[3])
        : "r"(a[0]), "r"(a[1]), "r"(a[2]), "r"(a[3]), "r"(b[0]), "r"(b[1]));
}
__device__ __forceinline__ void mma_s8(int* d, const uint32_t* a, const uint32_t* b) {
    asm volatile(
        "mma.sync.aligned.m16n8k32.row.col.s32.s8.s8.s32 "
        "{%0,%1,%2,%3}, {%4,%5,%6,%7}, {%8,%9}, {%0,%1,%2,%3};"
        : "+r"(d[0]), "+r"(d[1]), "+r"(d[2]), "+r"(d[3])
        : "r"(a[0]), "r"(a[1]), "r"(a[2]), "r"(a[3]), "r"(b[0]), "r"(b[1]));
}
__device__ __forceinline__ void cpa16(uint32_t dst, const void* src) {
    asm volatile("cp.async.cg.shared.global [%0], [%1], 16;"
                 :: "r"(dst), "l"(src) : "memory");
}
__device__ __forceinline__ void cpa_commit() {
    asm volatile("cp.async.commit_group;" ::: "memory");
}
template <int N> __device__ __forceinline__ void cpa_wait() {
    asm volatile("cp.async.wait_group %0;" :: "n"(N) : "memory");
}

// ---------------------------------------------------------------------------
// int8 two-level GEMM: C = diag(sa) [ (A1+A2/128)(B1+B2/128)^T ] diag(sb)
// block 128x128, BK=32 bytes, 4-stage cp.async, 256 thr (8 warps, 4x2),
// warp tile 32x64, IMMA m16n8k32, 3 terms (hi*hi -> acc_hi, cross -> acc_mid).
// A planes [M][K] s8 row-major; B planes [N][K] s8 row-major.
// MODE 0: scatter into g_q/g_kv heads. MODE 1: C = Cout [M][2048] fp32.
// ---------------------------------------------------------------------------
#define QLD 48                 // smem bytes per row (32 data + 16 pad)
#define QSTG (128 * QLD)       // bytes per plane per stage
#define NQS 4
#define QSMEM (NQS * 4 * QSTG) // 98304 B

template <int MODE>
__global__ __launch_bounds__(256, 1) void gemm_q(
    const char* __restrict__ A1, const char* __restrict__ A2,
    const float* __restrict__ sa,
    const char* __restrict__ B1, const char* __restrict__ B2,
    const float* __restrict__ sb,
    float* __restrict__ Cout)
{
    extern __shared__ char smq[];
    const uint32_t sbase = smem_u32(smq);
    const int tid = threadIdx.x;
    const int lane = tid & 31, warp = tid >> 5;
    const int m_warp = (warp & 3) * 32, n_warp = (warp >> 2) * 64;
    const int n0 = blockIdx.x * 128, m0 = blockIdx.y * 128;
    const int K = 2048;

    // loader: 1 cpa16 per plane per stage per thread (128 rows x 2 segs)
    const int lrow = tid >> 1, lseg = tid & 1;
    const char* pA1 = A1 + (size_t)(m0 + lrow) * K + lseg * 16;
    const char* pA2 = A2 + (size_t)(m0 + lrow) * K + lseg * 16;
    const char* pB1 = B1 + (size_t)(n0 + lrow) * K + lseg * 16;
    const char* pB2 = B2 + (size_t)(n0 + lrow) * K + lseg * 16;
    const uint32_t sdst = (uint32_t)(lrow * QLD + lseg * 16);

    // ldmatrix lane addressing
    const uint32_t aoff = (uint32_t)((m_warp + (lane & 15)) * QLD + (lane >> 4) * 16);
    const uint32_t boff = (uint32_t)((n_warp + (lane & 7) + ((lane >> 4) & 1) * 8) * QLD
                                     + ((lane >> 3) & 1) * 16);

    int ach[2][8][4], acm[2][8][4];
#pragma unroll
    for (int mt = 0; mt < 2; mt++)
#pragma unroll
        for (int nt = 0; nt < 8; nt++)
#pragma unroll
            for (int e = 0; e < 4; e++) { ach[mt][nt][e] = 0; acm[mt][nt][e] = 0; }

    const int NC = K / 32;  // 64

#pragma unroll
    for (int p = 0; p < NQS - 1; p++) {
        uint32_t st = sbase + (uint32_t)(p * 4 * QSTG);
        cpa16(st + sdst, pA1 + p * 32);
        cpa16(st + QSTG + sdst, pA2 + p * 32);
        cpa16(st + 2 * QSTG + sdst, pB1 + p * 32);
        cpa16(st + 3 * QSTG + sdst, pB2 + p * 32);
        cpa_commit();
    }

    for (int c = 0; c < NC; c++) {
        const int s = c & (NQS - 1);
        cpa_wait<NQS - 2>();
        __syncthreads();
        const int cn = c + NQS - 1;
        if (cn < NC) {
            const int sn = cn & (NQS - 1);
            uint32_t st = sbase + (uint32_t)(sn * 4 * QSTG);
            cpa16(st + sdst, pA1 + cn * 32);
            cpa16(st + QSTG + sdst, pA2 + cn * 32);
            cpa16(st + 2 * QSTG + sdst, pB1 + cn * 32);
            cpa16(st + 3 * QSTG + sdst, pB2 + cn * 32);
        }
        cpa_commit();

        const uint32_t st = sbase + (uint32_t)(s * 4 * QSTG);
        uint32_t a1f[2][4], a2f[2][4];
        ldm4(a1f[0], st + aoff);
        ldm4(a1f[1], st + aoff + 16 * QLD);
        ldm4(a2f[0], st + QSTG + aoff);
        ldm4(a2f[1], st + QSTG + aoff + 16 * QLD);
#pragma unroll
        for (int g = 0; g < 4; g++) {
            uint32_t b1f[4], b2f[4];
            ldm4(b1f, st + 2 * QSTG + boff + (uint32_t)(g * 16 * QLD));
            ldm4(b2f, st + 3 * QSTG + boff + (uint32_t)(g * 16 * QLD));
#pragma unroll
            for (int mt = 0; mt < 2; mt++) {
                mma_s8(ach[mt][2 * g + 0], a1f[mt], b1f + 0);
                mma_s8(ach[mt][2 * g + 1], a1f[mt], b1f + 2);
                mma_s8(acm[mt][2 * g + 0], a1f[mt], b2f + 0);
                mma_s8(acm[mt][2 * g + 1], a1f[mt], b2f + 2);
                mma_s8(acm[mt][2 * g + 0], a2f[mt], b1f + 0);
                mma_s8(acm[mt][2 * g + 1], a2f[mt], b1f + 2);
            }
        }
    }

    // epilogue
    const int r = lane >> 2, cq = (lane & 3) * 2;
    const int headn = (n0 + n_warp) >> 7;          // MODE 0: head id (0..31)
    const int hb = (n0 + n_warp) & 127;
#pragma unroll
    for (int mt = 0; mt < 2; mt++) {
        const int row0 = m0 + m_warp + mt * 16 + r;
        const int row1 = row0 + 8;
        const float sa0 = sa[row0], sa1 = sa[row1];
        float *d0, *d1;
        if (MODE == 1) {
            d0 = Cout + (size_t)row0 * 2048 + n0 + n_warp + cq;
            d1 = Cout + (size_t)row1 * 2048 + n0 + n_warp + cq;
        } else {
            float* base = (headn < 16) ? g_q : g_kv;
            const int hj = (headn < 16) ? headn : headn - 16;
            d0 = base + (((size_t)((row0 >> 11) * 16 + hj)) * TT + (row0 & 2047)) * HDIM + hb + cq;
            d1 = base + (((size_t)((row1 >> 11) * 16 + hj)) * TT + (row1 & 2047)) * HDIM + hb + cq;
        }
#pragma unroll
        for (int nt = 0; nt < 8; nt++) {
            const int col = n0 + n_warp + nt * 8 + cq;
            const float2 sbv = *(const float2*)(sb + col);
            float v00 = (float)ach[mt][nt][0] + (float)acm[mt][nt][0] * 0.0078125f;
            float v01 = (float)ach[mt][nt][1] + (float)acm[mt][nt][1] * 0.0078125f;
            float v10 = (float)ach[mt][nt][2] + (float)acm[mt][nt][2] * 0.0078125f;
            float v11 = (float)ach[mt][nt][3] + (float)acm[mt][nt][3] * 0.0078125f;
            *(float2*)(d0 + nt * 8) = make_float2(sa0 * sbv.x * v00, sa0 * sbv.y * v01);
            *(float2*)(d1 + nt * 8) = make_float2(sa1 * sbv.x * v10, sa1 * sbv.y * v11);
        }
    }
}

// ---------------------------------------------------------------------------
// prep: plain transpose (weights -> [N][K] fp32) + rowwise two-level quant
// ---------------------------------------------------------------------------
__global__ void transpose_f32(const float* __restrict__ src, float* __restrict__ dst,
                              int R, int C)
{
    __shared__ float tsm[32][33];
    const int p = blockIdx.z;
    src += (size_t)p * R * C;
    dst += (size_t)p * (size_t)C * 2048;
    int c0 = blockIdx.x * 32, r0 = blockIdx.y * 32;
#pragma unroll
    for (int j = threadIdx.y; j < 32; j += 8)
        tsm[j][threadIdx.x] = src[(size_t)(r0 + j) * C + c0 + threadIdx.x];
    __syncthreads();
#pragma unroll
    for (int j = threadIdx.y; j < 32; j += 8)
        dst[(size_t)(c0 + j) * 2048 + r0 + threadIdx.x] = tsm[threadIdx.x][j];
}

__global__ __launch_bounds__(256) void quant_rows(
    const float* __restrict__ src, char* __restrict__ q1, char* __restrict__ q2,
    float* __restrict__ sc)
{
    __shared__ float wm[8];
    const int row = blockIdx.x, tid = threadIdx.x;
    const float* rp = src + (size_t)row * 2048;
    float4 v0 = ((const float4*)rp)[tid * 2];
    float4 v1 = ((const float4*)rp)[tid * 2 + 1];
    float xs[8] = {v0.x, v0.y, v0.z, v0.w, v1.x, v1.y, v1.z, v1.w};
    float mx = 0.0f;
#pragma unroll
    for (int i = 0; i < 8; i++) mx = fmaxf(mx, fabsf(xs[i]));
#pragma unroll
    for (int d = 16; d; d >>= 1) mx = fmaxf(mx, __shfl_xor_sync(0xffffffffu, mx, d));
    if ((tid & 31) == 0) wm[tid >> 5] = mx;
    __syncthreads();
    float m = fmaxf(fmaxf(fmaxf(wm[0], wm[1]), fmaxf(wm[2], wm[3])),
                    fmaxf(fmaxf(wm[4], wm[5]), fmaxf(wm[6], wm[7])));
    const float inv = (m > 0.0f) ? 127.0f / m : 0.0f;
    if (tid == 0) sc[row] = (m > 0.0f) ? m / 127.0f : 1.0f;
    uint32_t p1[2] = {0, 0}, p2[2] = {0, 0};
#pragma unroll
    for (int i = 0; i < 8; i++) {
        float v = xs[i] * inv;
        int i1 = __float2int_rn(v);
        int i2 = __float2int_rn((v - (float)i1) * 128.0f);
        p1[i >> 2] |= ((uint32_t)i1 & 0xFFu) << ((i & 3) * 8);
        p2[i >> 2] |= ((uint32_t)i2 & 0xFFu) << ((i & 3) * 8);
    }
    ((uint2*)(q1 + (size_t)row * 2048))[tid] = make_uint2(p1[0], p1[1]);
    ((uint2*)(q2 + (size_t)row * 2048))[tid] = make_uint2(p2[0], p2[1]);
}

// ---------------------------------------------------------------------------
// RoPE
// ---------------------------------------------------------------------------
struct TsTab { double ts[64]; };

__global__ void rope_table(const int* __restrict__ pos, TsTab tt)
{
    int idx = blockIdx.x * blockDim.x + threadIdx.x;
    int i = idx & 63;
    int t = (idx >> 6) & (TT - 1);
    int b = idx >> 17;
    double th = (double)pos[b * TT + t] * tt.ts[i];
    double sd, cd;
    sincos(th, &sd, &cd);
    g_tab[idx] = make_float2((float)cd, (float)sd);
}

__global__ void rope_apply(float* __restrict__ buf, int nheads, int strideHeads,
                           float scale)
{
    int idx = blockIdx.x * blockDim.x + threadIdx.x;
    int i = idx & 63;
    int t = (idx >> 6) & (TT - 1);
    int rest = idx >> 17;
    int hd = rest % nheads;
    int b = rest / nheads;
    if (b >= BB) return;
    float2 cs = g_tab[((size_t)b * TT + t) * 64 + i];
    size_t base = (((size_t)(b * strideHeads + hd)) * TT + t) * HDIM;
    float f = buf[base + i];
    float se = buf[base + 64 + i];
    buf[base + i] = (f * cs.x - se * cs.y) * scale;
    buf[base + 64 + i] = (se * cs.x + f * cs.y) * scale;
}

// ---------------------------------------------------------------------------
// softcap + static-shift exp, MUFU-free.
// ---------------------------------------------------------------------------
__device__ __forceinline__ float softexp(float x, bool valid) {
    float y = x * 0.02f;
    float u = y * y;
    float pl = fmaf(u, -0.00886324f, 0.02186949f);
    pl = fmaf(u, pl, -0.05396825f);
    pl = fmaf(u, pl, 0.13333333f);
    pl = fmaf(u, pl, -0.33333333f);
    pl = fmaf(u, pl, 1.0f);
    float cap = x * pl;
    if (fabsf(y) > 0.58f) {
        float t = __expf(2.0f * fabsf(y));
        float th = 1.0f - __fdividef(2.0f, t + 1.0f);
        cap = copysignf(50.0f * th, x);
    }
    float t = fmaf(cap, 1.442695041f, -18.755036f);
    float rr = t + 12582912.0f;
    float nf = rr - 12582912.0f;
    float f = t - nf;
    float e = fmaf(f, 1.5403530e-4f, 1.3333558e-3f);
    e = fmaf(f, e, 9.6181291e-3f);
    e = fmaf(f, e, 5.5504109e-2f);
    e = fmaf(f, e, 2.4022651e-1f);
    e = fmaf(f, e, 6.9314718e-1f);
    e = fmaf(f, e, 1.0f);
    int ni = (__float_as_int(rr) & 0x7FFFFF) - 0x400000;
    float sc = __int_as_float((ni + 127) << 23);
    return valid ? e * sc : 0.0f;
}

// ---------------------------------------------------------------------------
// Tensor-core flash attention (mma.sync tf32). g_enc plain fp32 (quantized
// afterward for the int8 outproj).
// ---------------------------------------------------------------------------
#define KTLD 72
#define VSLD 136
#define PSLD 68
#define QSLD 132
#define SMEM_ATTN ((128 * KTLD + 64 * VSLD + 64 * PSLD) * 4)

__global__ __launch_bounds__(128, 2) void attn_kernel()
{
    extern __shared__ float sm[];
    float* Kt = sm;
    float* Vs = sm + 128 * KTLD;
    float* Ps = Vs + 64 * VSLD;
    float* Qs = sm;

    const int tid = threadIdx.x;
    const int lane = tid & 31, warp = tid >> 5;
    const int wm = warp * 16;
    const int lr = lane >> 2, lc = (lane & 3) * 2;
    const int qi = gridDim.x - 1 - blockIdx.x;
    const int q0 = qi * 64;
    const int n = blockIdx.y, b = blockIdx.z;
    const int kvh = n >> 1;
    const float* Qp = g_q + ((size_t)(b * NHEADS + n)) * TT * HDIM;
    const float* Kp = g_kv + ((size_t)(b * 16 + kvh)) * TT * HDIM;
    const float* Vp = g_kv + ((size_t)(b * 16 + 8 + kvh)) * TT * HDIM;

    {
        int c = tid & 63, k4 = (tid >> 6) << 2;
#pragma unroll
        for (int kb = 0; kb < 16; kb++) {
            int k = kb * 8 + k4;
            float4 v = *(const float4*)(Qp + (size_t)(q0 + c) * HDIM + k);
            v.x = tf32r(v.x); v.y = tf32r(v.y); v.z = tf32r(v.z); v.w = tf32r(v.w);
            *(float4*)&Qs[c * QSLD + k] = v;
        }
    }
    __syncthreads();
    uint32_t qf[16][4];
    {
        uint32_t baseQ = smem_u32(Qs);
        int r = lane & 15, cA = (lane & 16) ? 4 : 0;
        uint32_t addr = baseQ + (uint32_t)((wm + r) * QSLD + cA) * 4u;
#pragma unroll
        for (int k8 = 0; k8 < 16; k8++) ldm4(qf[k8], addr + (uint32_t)k8 * 32u);
    }
    __syncthreads();

    float o[16][4];
#pragma unroll
    for (int nt = 0; nt < 16; nt++)
#pragma unroll
        for (int e = 0; e < 4; e++) o[nt][e] = 0.0f;
    float ls0 = 0.0f, ls1 = 0.0f;

    const int gr0 = q0 + wm + lr;
    const int gr1 = gr0 + 8;
    const uint32_t psAddr = smem_u32(Ps) +
        (uint32_t)(((wm + (lane & 15)) * PSLD + ((lane >> 4) << 2)) * 4);

    for (int tile = 0; tile <= qi; tile++) {
        const int s0 = tile * 64;
        {
            int c = tid & 63, k4 = (tid >> 6) << 2;
#pragma unroll
            for (int kb = 0; kb < 16; kb++) {
                int k = kb * 8 + k4;
                float4 v = *(const float4*)(Kp + (size_t)(s0 + c) * HDIM + k);
                Kt[(k + 0) * KTLD + c] = tf32r(v.x);
                Kt[(k + 1) * KTLD + c] = tf32r(v.y);
                Kt[(k + 2) * KTLD + c] = tf32r(v.z);
                Kt[(k + 3) * KTLD + c] = tf32r(v.w);
            }
#pragma unroll
            for (int it = 0; it < 16; it++) {
                int idx = tid + it * 128;
                int s = idx >> 5, c4 = (idx & 31) << 2;
                float4 v = *(const float4*)(Vp + (size_t)(s0 + s) * HDIM + c4);
                v.x = tf32r(v.x); v.y = tf32r(v.y); v.z = tf32r(v.z); v.w = tf32r(v.w);
                *(float4*)&Vs[s * VSLD + c4] = v;
            }
        }
        __syncthreads();

        float sa[8][4];
#pragma unroll
        for (int nt = 0; nt < 8; nt++)
#pragma unroll
            for (int e = 0; e < 4; e++) sa[nt][e] = 0.0f;
#pragma unroll
        for (int k8 = 0; k8 < 16; k8++) {
            const int kr0 = (k8 * 8 + (lane & 3)) * KTLD + lr;
            uint32_t bfr[8][2];
#pragma unroll
            for (int nt = 0; nt < 8; nt++) {
                bfr[nt][0] = __float_as_uint(Kt[kr0 + nt * 8]);
                bfr[nt][1] = __float_as_uint(Kt[kr0 + 4 * KTLD + nt * 8]);
            }
#pragma unroll
            for (int nt = 0; nt < 8; nt++) mma_tf32(sa[nt], qf[k8], bfr[nt]);
        }

        float* psrow0 = Ps + (wm + lr) * PSLD + lc;
        float* psrow1 = psrow0 + 8 * PSLD;
#pragma unroll
        for (int nt = 0; nt < 8; nt++) {
            int c = s0 + nt * 8 + lc;
            float p00 = softexp(sa[nt][0], c <= gr0);
            float p01 = softexp(sa[nt][1], c + 1 <= gr0);
            float p10 = softexp(sa[nt][2], c <= gr1);
            float p11 = softexp(sa[nt][3], c + 1 <= gr1);
            ls0 += p00 + p01;
            ls1 += p10 + p11;
            *(float2*)(psrow0 + nt * 8) = make_float2(tf32r(p00), tf32r(p01));
            *(float2*)(psrow1 + nt * 8) = make_float2(tf32r(p10), tf32r(p11));
        }
        __syncthreads();

#pragma unroll
        for (int k8 = 0; k8 < 8; k8++) {
            uint32_t pf[4];
            ldm4(pf, psAddr + (uint32_t)k8 * 32u);
            const int vr0 = (k8 * 8 + (lane & 3)) * VSLD + lr;
#pragma unroll
            for (int nt = 0; nt < 16; nt++) {
                uint32_t bb[2];
                bb[0] = __float_as_uint(Vs[vr0 + nt * 8]);
                bb[1] = __float_as_uint(Vs[vr0 + 4 * VSLD + nt * 8]);
                mma_tf32(o[nt], pf, bb);
            }
        }
        __syncthreads();
    }

    ls0 += __shfl_xor_sync(0xffffffffu, ls0, 1);
    ls0 += __shfl_xor_sync(0xffffffffu, ls0, 2);
    ls1 += __shfl_xor_sync(0xffffffffu, ls1, 1);
    ls1 += __shfl_xor_sync(0xffffffffu, ls1, 2);
    float i0 = 1.0f / ls0, i1 = 1.0f / ls1;
    float* er0 = g_enc + ((size_t)b * TT + gr0) * (NHEADS * HDIM) + n * HDIM + lc;
    float* er1 = g_enc + ((size_t)b * TT + gr1) * (NHEADS * HDIM) + n * HDIM + lc;
#pragma unroll
    for (int nt = 0; nt < 16; nt++) {
        *(float2*)(er0 + nt * 8) = make_float2(o[nt][0] * i0, o[nt][1] * i0);
        *(float2*)(er1 + nt * 8) = make_float2(o[nt][2] * i1, o[nt][3] * i1);
    }
}

// ---------------------------------------------------------------------------
extern "C" void kernel_launch(void* const* d_in, const int* in_sizes, int n_in,
                              void* d_out, int out_size)
{
    const float* x = (const float*)d_in[0];
    const int* positions = (const int*)d_in[1];
    // d_in[2] = attn_mask (causal) — analytic
    const float* w_q = (const float*)d_in[3];
    const float* w_kv = (const float*)d_in[4];
    const float* w_out = (const float*)d_in[5];
    float* out = (float*)d_out;

    float *wt, *wot, *qb, *kvb, *encb;
    cudaGetSymbolAddress((void**)&wt, g_wt);
    cudaGetSymbolAddress((void**)&wot, g_wot);
    cudaGetSymbolAddress((void**)&qb, g_q);
    cudaGetSymbolAddress((void**)&kvb, g_kv);
    cudaGetSymbolAddress((void**)&encb, g_enc);
    char *xq1, *xq2, *wtq1, *wtq2, *woq1, *woq2, *eq1, *eq2;
    float *xs, *wts, *wos, *es;
    cudaGetSymbolAddress((void**)&xq1, g_xq1);
    cudaGetSymbolAddress((void**)&xq2, g_xq2);
    cudaGetSymbolAddress((void**)&wtq1, g_wtq1);
    cudaGetSymbolAddress((void**)&wtq2, g_wtq2);
    cudaGetSymbolAddress((void**)&woq1, g_woq1);
    cudaGetSymbolAddress((void**)&woq2, g_woq2);
    cudaGetSymbolAddress((void**)&eq1, g_eq1);
    cudaGetSymbolAddress((void**)&eq2, g_eq2);
    cudaGetSymbolAddress((void**)&xs, g_xs);
    cudaGetSymbolAddress((void**)&wts, g_wts);
    cudaGetSymbolAddress((void**)&wos, g_wos);
    cudaGetSymbolAddress((void**)&es, g_es);

    TsTab tt;
    for (int i = 0; i < 64; i++) tt.ts[i] = pow(10000.0, -(double)i / 64.0);

    // prep: transposes + two-level int8 quantization
    transpose_f32<<<dim3(4, 64, 16), dim3(32, 8)>>>(w_q, wt, 2048, 128);
    transpose_f32<<<dim3(4, 64, 16), dim3(32, 8)>>>(
        w_kv, wt + (size_t)2048 * 2048, 2048, 128);
    transpose_f32<<<dim3(64, 64, 1), dim3(32, 8)>>>(w_out, wot, 2048, 2048);
    quant_rows<<<4096, 256>>>(x, xq1, xq2, xs);
    quant_rows<<<4096, 256>>>(wt, wtq1, wtq2, wts);
    quant_rows<<<2048, 256>>>(wot, woq1, woq2, wos);
    rope_table<<<(BB * TT * 64) / 256, 256>>>(positions, tt);

    // merged QKV projection (int8 IMMA)
    cudaFuncSetAttribute(gemm_q<0>, cudaFuncAttributeMaxDynamicSharedMemorySize,
                         QSMEM);
    cudaFuncSetAttribute(gemm_q<1>, cudaFuncAttributeMaxDynamicSharedMemorySize,
                         QSMEM);
    gemm_q<0><<<dim3(32, 32), 256, QSMEM>>>(xq1, xq2, xs, wtq1, wtq2, wts, nullptr);

    rope_apply<<<(BB * NHEADS * TT * 64) / 256, 256>>>(
        qb, NHEADS, NHEADS, 0.08838834764831845f);
    rope_apply<<<(BB * NKVH * TT * 64) / 256, 256>>>(
        kvb, NKVH, 16, 1.0f);

    cudaFuncSetAttribute(attn_kernel, cudaFuncAttributeMaxDynamicSharedMemorySize,
                         SMEM_ATTN);
    attn_kernel<<<dim3(TT / 64, NHEADS, BB), 128, SMEM_ATTN>>>();

    // output projection (int8 IMMA)
    quant_rows<<<4096, 256>>>(encb, eq1, eq2, es);
    gemm_q<1><<<dim3(16, 32), 256, QSMEM>>>(eq1, eq2, es, woq1, woq2, wos, out);
}

// round 8
// speedup vs baseline: 4.0576x; 4.0576x over previous
#include <cuda_runtime.h>
#include <cuda_fp16.h>
#include <math.h>
#include <stdint.h>

#define BB 2
#define TT 2048
#define DD 2048
#define NHEADS 16
#define NKVH 8
#define HDIM 128

// Scratch (allocation-free rule: __device__ globals)
static __device__ float g_q[(size_t)BB * NHEADS * TT * HDIM];   // [b][n][t][h] fp32 (rope target)
static __device__ float g_kv[(size_t)BB * 16 * TT * HDIM];      // [b][j][t][h] fp32, j<8=K, j>=8=V
static __device__ float2 g_tab[(size_t)BB * TT * 64];           // rope cos/sin
static __device__ __half g_xh[(size_t)4096 * 2048];             // x fp16
static __device__ __half g_wth[(size_t)4096 * 2048];            // [q;kv] weights^T fp16 [nglob][k]
static __device__ __half g_woth[(size_t)2048 * 2048];           // w_out^T fp16 [n][k]
static __device__ __half g_ench[(size_t)4096 * 2048];           // encoded fp16 [b*T+t][n*128+h]

// ---------------------------------------------------------------------------
// helpers
// ---------------------------------------------------------------------------
__device__ __forceinline__ uint32_t smem_u32(const void* p) {
    return (uint32_t)__cvta_generic_to_shared(p);
}
__device__ __forceinline__ void ldm4(uint32_t* r, uint32_t addr) {
    asm volatile("ldmatrix.sync.aligned.m8n8.x4.shared.b16 {%0,%1,%2,%3}, [%4];"
                 : "=r"(r[0]), "=r"(r[1]), "=r"(r[2]), "=r"(r[3]) : "r"(addr));
}
__device__ __forceinline__ void ldm4t(uint32_t* r, uint32_t addr) {
    asm volatile("ldmatrix.sync.aligned.m8n8.x4.trans.shared.b16 {%0,%1,%2,%3}, [%4];"
                 : "=r"(r[0]), "=r"(r[1]), "=r"(r[2]), "=r"(r[3]) : "r"(addr));
}
__device__ __forceinline__ void mma_f16(float* d, const uint32_t* a, const uint32_t* b) {
    asm volatile(
        "mma.sync.aligned.m16n8k16.row.col.f32.f16.f16.f32 "
        "{%0,%1,%2,%3}, {%4,%5,%6,%7}, {%8,%9}, {%0,%1,%2,%3};"
        : "+f"(d[0]), "+f"(d[1]), "+f"(d[2]), "+f"(d[3])
        : "r"(a[0]), "r"(a[1]), "r"(a[2]), "r"(a[3]), "r"(b[0]), "r"(b[1]));
}
__device__ __forceinline__ void cpa16(uint32_t dst, const void* src) {
    asm volatile("cp.async.cg.shared.global [%0], [%1], 16;"
                 :: "r"(dst), "l"(src) : "memory");
}
__device__ __forceinline__ void cpa_commit() {
    asm volatile("cp.async.commit_group;" ::: "memory");
}
template <int N> __device__ __forceinline__ void cpa_wait() {
    asm volatile("cp.async.wait_group %0;" :: "n"(N) : "memory");
}

// ---------------------------------------------------------------------------
// fp16 GEMM: 128x128 tile, BK=32 halfs, 4-stage cp.async, 256 thr (8 warps,
// 4x2), warp tile 32x64, mma m16n8k16 f32 accum. A [M][K], Bt [N][K] fp16.
// MODE 0: scatter fp32 into g_q/g_kv heads. MODE 1: fp32 Cout [M][2048].
// ---------------------------------------------------------------------------
#define HLD 40                  // halfs per smem row (32 data + 8 pad) = 80 B
#define H_STG (128 * HLD)       // halfs per operand per stage
#define NHS 4
#define HSMEM (NHS * 2 * H_STG * 2)  // 81920 B

template <int MODE>
__global__ __launch_bounds__(256, 2) void gemm_h(
    const __half* __restrict__ A, const __half* __restrict__ Bt,
    float* __restrict__ Cout)
{
    extern __shared__ __half smh[];
    __half* As = smh;                    // [NHS][128][HLD]
    __half* Bs = smh + NHS * H_STG;
    const int tid = threadIdx.x;
    const int lane = tid & 31, warp = tid >> 5;
    const int m_warp = (warp & 3) * 32, n_warp = (warp >> 2) * 64;
    const int n0 = blockIdx.x * 128, m0 = blockIdx.y * 128;
    const int K = 2048;

    // loader: row = tid>>2 (0..63 / +64), seg = tid&3 (8 halfs = 16 B)
    const int lrow = tid >> 2, lseg = tid & 3;
    const __half* pA = A + (size_t)(m0 + lrow) * K + lseg * 8;
    const __half* pA2 = pA + (size_t)64 * K;
    const __half* pB = Bt + (size_t)(n0 + lrow) * K + lseg * 8;
    const __half* pB2 = pB + (size_t)64 * K;
    const uint32_t sd1 = (uint32_t)(lrow * HLD + lseg * 8) * 2u;
    const uint32_t sd2 = (uint32_t)((lrow + 64) * HLD + lseg * 8) * 2u;
    const uint32_t aBase = smem_u32(As), bBase = smem_u32(Bs);

    // ldmatrix lane addressing
    const uint32_t aoff =
        (uint32_t)((m_warp + (lane & 15)) * HLD + (lane >> 4) * 8) * 2u;
    const uint32_t boff =
        (uint32_t)((n_warp + (lane >> 4) * 8 + (lane & 7)) * HLD +
                   ((lane >> 3) & 1) * 8) * 2u;

    float acc[2][8][4];
#pragma unroll
    for (int mt = 0; mt < 2; mt++)
#pragma unroll
        for (int nt = 0; nt < 8; nt++)
#pragma unroll
            for (int e = 0; e < 4; e++) acc[mt][nt][e] = 0.0f;

    const int NC = K / 32;  // 64

#pragma unroll
    for (int p = 0; p < NHS - 1; p++) {
        uint32_t ab = aBase + (uint32_t)(p * H_STG) * 2u;
        uint32_t bb = bBase + (uint32_t)(p * H_STG) * 2u;
        cpa16(ab + sd1, pA + p * 32);
        cpa16(ab + sd2, pA2 + p * 32);
        cpa16(bb + sd1, pB + p * 32);
        cpa16(bb + sd2, pB2 + p * 32);
        cpa_commit();
    }

    for (int c = 0; c < NC; c++) {
        const int s = c & (NHS - 1);
        cpa_wait<NHS - 2>();
        __syncthreads();
        const int cn = c + NHS - 1;
        if (cn < NC) {
            const int sn = cn & (NHS - 1);
            uint32_t ab = aBase + (uint32_t)(sn * H_STG) * 2u;
            uint32_t bb = bBase + (uint32_t)(sn * H_STG) * 2u;
            cpa16(ab + sd1, pA + cn * 32);
            cpa16(ab + sd2, pA2 + cn * 32);
            cpa16(bb + sd1, pB + cn * 32);
            cpa16(bb + sd2, pB2 + cn * 32);
        }
        cpa_commit();

        const uint32_t aSt = aBase + (uint32_t)(s * H_STG) * 2u + aoff;
        const uint32_t bSt = bBase + (uint32_t)(s * H_STG) * 2u + boff;
#pragma unroll
        for (int kb = 0; kb < 2; kb++) {
            uint32_t af[2][4];
            ldm4(af[0], aSt + (uint32_t)kb * 32u);
            ldm4(af[1], aSt + (uint32_t)(16 * HLD * 2) + (uint32_t)kb * 32u);
#pragma unroll
            for (int g = 0; g < 4; g++) {
                uint32_t bf[4];
                ldm4(bf, bSt + (uint32_t)(g * 16 * HLD * 2) + (uint32_t)kb * 32u);
#pragma unroll
                for (int mt = 0; mt < 2; mt++) {
                    mma_f16(acc[mt][2 * g + 0], af[mt], bf + 0);
                    mma_f16(acc[mt][2 * g + 1], af[mt], bf + 2);
                }
            }
        }
    }

    // epilogue
    const int r = lane >> 2, cq = (lane & 3) * 2;
    const int headn = (n0 + n_warp) >> 7;
    const int hb = (n0 + n_warp) & 127;
#pragma unroll
    for (int mt = 0; mt < 2; mt++) {
        const int row0 = m0 + m_warp + mt * 16 + r;
        const int row1 = row0 + 8;
        float *d0, *d1;
        if (MODE == 1) {
            d0 = Cout + (size_t)row0 * 2048 + n0 + n_warp + cq;
            d1 = Cout + (size_t)row1 * 2048 + n0 + n_warp + cq;
        } else {
            float* base = (headn < 16) ? g_q : g_kv;
            const int hj = (headn < 16) ? headn : headn - 16;
            d0 = base + (((size_t)((row0 >> 11) * 16 + hj)) * TT + (row0 & 2047)) * HDIM + hb + cq;
            d1 = base + (((size_t)((row1 >> 11) * 16 + hj)) * TT + (row1 & 2047)) * HDIM + hb + cq;
        }
#pragma unroll
        for (int nt = 0; nt < 8; nt++) {
            *(float2*)(d0 + nt * 8) = make_float2(acc[mt][nt][0], acc[mt][nt][1]);
            *(float2*)(d1 + nt * 8) = make_float2(acc[mt][nt][2], acc[mt][nt][3]);
        }
    }
}

// ---------------------------------------------------------------------------
// prep: fp16 convert-copy (x) + fp16 transposes (weights -> [N][K])
// ---------------------------------------------------------------------------
__global__ void conv_half(const float* __restrict__ src, __half* __restrict__ dst)
{
    int i = blockIdx.x * 256 + threadIdx.x;
    float4 v = ((const float4*)src)[i];
    ((__half2*)dst)[i * 2] = __floats2half2_rn(v.x, v.y);
    ((__half2*)dst)[i * 2 + 1] = __floats2half2_rn(v.z, v.w);
}

// dst[plane][c][r] = half(src[plane][r][c]); dst row stride 2048
__global__ void transpose_half(const float* __restrict__ src, __half* __restrict__ dst,
                               int R, int C)
{
    __shared__ float tsm[32][33];
    const int p = blockIdx.z;
    src += (size_t)p * R * C;
    dst += (size_t)p * (size_t)C * 2048;
    int c0 = blockIdx.x * 32, r0 = blockIdx.y * 32;
#pragma unroll
    for (int j = threadIdx.y; j < 32; j += 8)
        tsm[j][threadIdx.x] = src[(size_t)(r0 + j) * C + c0 + threadIdx.x];
    __syncthreads();
#pragma unroll
    for (int j = threadIdx.y; j < 32; j += 8)
        dst[(size_t)(c0 + j) * 2048 + r0 + threadIdx.x] = __float2half_rn(tsm[threadIdx.x][j]);
}

// ---------------------------------------------------------------------------
// RoPE (fp32 buffers)
// ---------------------------------------------------------------------------
struct TsTab { double ts[64]; };

__global__ void rope_table(const int* __restrict__ pos, TsTab tt)
{
    int idx = blockIdx.x * blockDim.x + threadIdx.x;
    int i = idx & 63;
    int t = (idx >> 6) & (TT - 1);
    int b = idx >> 17;
    double th = (double)pos[b * TT + t] * tt.ts[i];
    double sd, cd;
    sincos(th, &sd, &cd);
    g_tab[idx] = make_float2((float)cd, (float)sd);
}

__global__ void rope_apply(float* __restrict__ buf, int nheads, int strideHeads,
                           float scale)
{
    int idx = blockIdx.x * blockDim.x + threadIdx.x;
    int i = idx & 63;
    int t = (idx >> 6) & (TT - 1);
    int rest = idx >> 17;
    int hd = rest % nheads;
    int b = rest / nheads;
    if (b >= BB) return;
    float2 cs = g_tab[((size_t)b * TT + t) * 64 + i];
    size_t base = (((size_t)(b * strideHeads + hd)) * TT + t) * HDIM;
    float f = buf[base + i];
    float se = buf[base + 64 + i];
    buf[base + i] = (f * cs.x - se * cs.y) * scale;
    buf[base + 64 + i] = (se * cs.x + f * cs.y) * scale;
}

// ---------------------------------------------------------------------------
// MUFU-free softcap + exp (arg clamped to [-80, 0])
// ---------------------------------------------------------------------------
__device__ __forceinline__ float softcap(float x) {
    float y = x * 0.02f;
    float u = y * y;
    float pl = fmaf(u, -0.00886324f, 0.02186949f);
    pl = fmaf(u, pl, -0.05396825f);
    pl = fmaf(u, pl, 0.13333333f);
    pl = fmaf(u, pl, -0.33333333f);
    pl = fmaf(u, pl, 1.0f);
    float cap = x * pl;
    if (fabsf(y) > 0.58f) {
        float t = __expf(2.0f * fabsf(y));
        float th = 1.0f - __fdividef(2.0f, t + 1.0f);
        cap = copysignf(50.0f * th, x);
    }
    return cap;
}
__device__ __forceinline__ float expfast(float a) {  // a in [-80, 0]
    float t = a * 1.442695041f;
    float rr = t + 12582912.0f;
    float nf = rr - 12582912.0f;
    float f = t - nf;
    float e = fmaf(f, 1.5403530e-4f, 1.3333558e-3f);
    e = fmaf(f, e, 9.6181291e-3f);
    e = fmaf(f, e, 5.5504109e-2f);
    e = fmaf(f, e, 2.4022651e-1f);
    e = fmaf(f, e, 6.9314718e-1f);
    e = fmaf(f, e, 1.0f);
    int ni = (__float_as_int(rr) & 0x7FFFFF) - 0x400000;
    return e * __int_as_float((ni + 127) << 23);
}

// ---------------------------------------------------------------------------
// fp16 flash attention: 64 q-rows/block (4 warps x 16), KV tiles of 64,
// mma m16n8k16 for S and PV, online softmax (fp16 P), causal, softcap.
// ---------------------------------------------------------------------------
#define KVLD 136   // halfs per K/V smem row (128 + 8 pad) = 272 B
#define PLD 72     // halfs per P row
#define SMEM_ATTN ((2 * 64 * KVLD + 64 * PLD) * 2)  // 44032 B

__global__ __launch_bounds__(128, 2) void attn_kernel()
{
    extern __shared__ __half smh[];
    __half* Ks = smh;                   // [64][KVLD]
    __half* Vs = smh + 64 * KVLD;       // [64][KVLD]
    __half* Ps = Vs + 64 * KVLD;        // [64][PLD]
    __half* Qs = smh;                   // alias (pre-loop staging)

    const int tid = threadIdx.x;
    const int lane = tid & 31, warp = tid >> 5;
    const int wm = warp * 16;
    const int lr = lane >> 2, lc = (lane & 3) * 2;
    const int qi = gridDim.x - 1 - blockIdx.x;  // heavy blocks first
    const int q0 = qi * 64;
    const int n = blockIdx.y, b = blockIdx.z;
    const int kvh = n >> 1;
    const float* Qp = g_q + ((size_t)(b * NHEADS + n)) * TT * HDIM;
    const float* Kp = g_kv + ((size_t)(b * 16 + kvh)) * TT * HDIM;
    const float* Vp = g_kv + ((size_t)(b * 16 + 8 + kvh)) * TT * HDIM;

    // ---- Q tile -> fp16 smem -> persistent A fragments
    {
#pragma unroll
        for (int it = 0; it < 16; it++) {
            int idx = tid + it * 128;
            int s = idx >> 5, c4 = (idx & 31) << 2;
            float4 v = *(const float4*)(Qp + (size_t)(q0 + s) * HDIM + c4);
            __half2* d = (__half2*)(Qs + s * KVLD + c4);
            d[0] = __floats2half2_rn(v.x, v.y);
            d[1] = __floats2half2_rn(v.z, v.w);
        }
    }
    __syncthreads();
    uint32_t qf[8][4];
    {
        uint32_t baseQ = smem_u32(Qs) +
            (uint32_t)((wm + (lane & 15)) * KVLD + (lane >> 4) * 8) * 2u;
#pragma unroll
        for (int kb = 0; kb < 8; kb++) ldm4(qf[kb], baseQ + (uint32_t)kb * 32u);
    }
    __syncthreads();

    float o[16][4];
#pragma unroll
    for (int nt = 0; nt < 16; nt++)
#pragma unroll
        for (int e = 0; e < 4; e++) o[nt][e] = 0.0f;
    float ls0 = 0.0f, ls1 = 0.0f, m0 = -1e30f, m1 = -1e30f;

    const int gr0 = q0 + wm + lr;
    const int gr1 = gr0 + 8;
    const uint32_t kBase = smem_u32(Ks) +
        (uint32_t)(((lane >> 4) * 8 + (lane & 7)) * KVLD + ((lane >> 3) & 1) * 8) * 2u;
    const uint32_t pBase = smem_u32(Ps) +
        (uint32_t)((wm + (lane & 15)) * PLD + (lane >> 4) * 8) * 2u;
    const uint32_t vBase = smem_u32(Vs) +
        (uint32_t)((lane & 15) * KVLD + (lane >> 4) * 8) * 2u;

    for (int tile = 0; tile <= qi; tile++) {
        const int s0 = tile * 64;
        // load K,V tiles (fp32 -> fp16)
#pragma unroll
        for (int it = 0; it < 16; it++) {
            int idx = tid + it * 128;
            int s = idx >> 5, c4 = (idx & 31) << 2;
            float4 kv4 = *(const float4*)(Kp + (size_t)(s0 + s) * HDIM + c4);
            __half2* dk = (__half2*)(Ks + s * KVLD + c4);
            dk[0] = __floats2half2_rn(kv4.x, kv4.y);
            dk[1] = __floats2half2_rn(kv4.z, kv4.w);
            float4 vv4 = *(const float4*)(Vp + (size_t)(s0 + s) * HDIM + c4);
            __half2* dv = (__half2*)(Vs + s * KVLD + c4);
            dv[0] = __floats2half2_rn(vv4.x, vv4.y);
            dv[1] = __floats2half2_rn(vv4.z, vv4.w);
        }
        __syncthreads();

        // S = Q K^T (per warp: 16 rows x 64 cols)
        float sa[8][4];
#pragma unroll
        for (int nt = 0; nt < 8; nt++)
#pragma unroll
            for (int e = 0; e < 4; e++) sa[nt][e] = 0.0f;
#pragma unroll
        for (int kb = 0; kb < 8; kb++) {
#pragma unroll
            for (int g = 0; g < 4; g++) {
                uint32_t bf[4];
                ldm4(bf, kBase + (uint32_t)(g * 16 * KVLD * 2) + (uint32_t)kb * 32u);
                mma_f16(sa[2 * g + 0], qf[kb], bf + 0);
                mma_f16(sa[2 * g + 1], qf[kb], bf + 2);
            }
        }

        // softcap + causal mask + online max
        float tm0 = -1e30f, tm1 = -1e30f;
#pragma unroll
        for (int nt = 0; nt < 8; nt++) {
            int c = s0 + nt * 8 + lc;
            sa[nt][0] = softcap(sa[nt][0]);
            sa[nt][1] = softcap(sa[nt][1]);
            sa[nt][2] = softcap(sa[nt][2]);
            sa[nt][3] = softcap(sa[nt][3]);
            tm0 = fmaxf(tm0, fmaxf(c <= gr0 ? sa[nt][0] : -1e30f,
                                   c + 1 <= gr0 ? sa[nt][1] : -1e30f));
            tm1 = fmaxf(tm1, fmaxf(c <= gr1 ? sa[nt][2] : -1e30f,
                                   c + 1 <= gr1 ? sa[nt][3] : -1e30f));
        }
        tm0 = fmaxf(tm0, __shfl_xor_sync(0xffffffffu, tm0, 1));
        tm0 = fmaxf(tm0, __shfl_xor_sync(0xffffffffu, tm0, 2));
        tm1 = fmaxf(tm1, __shfl_xor_sync(0xffffffffu, tm1, 1));
        tm1 = fmaxf(tm1, __shfl_xor_sync(0xffffffffu, tm1, 2));
        float mn0 = fmaxf(m0, tm0), mn1 = fmaxf(m1, tm1);
        float a0 = expfast(fmaxf(m0 - mn0, -80.0f));
        float a1 = expfast(fmaxf(m1 - mn1, -80.0f));
        m0 = mn0; m1 = mn1;
        ls0 *= a0; ls1 *= a1;
#pragma unroll
        for (int nt = 0; nt < 16; nt++) {
            o[nt][0] *= a0; o[nt][1] *= a0;
            o[nt][2] *= a1; o[nt][3] *= a1;
        }
        __half* pr0 = Ps + (wm + lr) * PLD + lc;
        __half* pr1 = pr0 + 8 * PLD;
#pragma unroll
        for (int nt = 0; nt < 8; nt++) {
            int c = s0 + nt * 8 + lc;
            float p0 = (c <= gr0) ? expfast(fmaxf(sa[nt][0] - mn0, -80.0f)) : 0.0f;
            float p1 = (c + 1 <= gr0) ? expfast(fmaxf(sa[nt][1] - mn0, -80.0f)) : 0.0f;
            float p2 = (c <= gr1) ? expfast(fmaxf(sa[nt][2] - mn1, -80.0f)) : 0.0f;
            float p3 = (c + 1 <= gr1) ? expfast(fmaxf(sa[nt][3] - mn1, -80.0f)) : 0.0f;
            ls0 += p0 + p1;
            ls1 += p2 + p3;
            *(__half2*)(pr0 + nt * 8) = __floats2half2_rn(p0, p1);
            *(__half2*)(pr1 + nt * 8) = __floats2half2_rn(p2, p3);
        }
        __syncthreads();

        // O += P V (per warp: 16 rows x 128 cols)
#pragma unroll
        for (int kb = 0; kb < 4; kb++) {
            uint32_t pf[4];
            ldm4(pf, pBase + (uint32_t)kb * 32u);
            const uint32_t vSt = vBase + (uint32_t)(kb * 16 * KVLD * 2);
#pragma unroll
            for (int j = 0; j < 8; j++) {
                uint32_t vf[4];
                ldm4t(vf, vSt + (uint32_t)(j * 16) * 2u);
                mma_f16(o[2 * j + 0], pf, vf + 0);
                mma_f16(o[2 * j + 1], pf, vf + 2);
            }
        }
        __syncthreads();
    }

    // finalize
    ls0 += __shfl_xor_sync(0xffffffffu, ls0, 1);
    ls0 += __shfl_xor_sync(0xffffffffu, ls0, 2);
    ls1 += __shfl_xor_sync(0xffffffffu, ls1, 1);
    ls1 += __shfl_xor_sync(0xffffffffu, ls1, 2);
    float i0 = 1.0f / ls0, i1 = 1.0f / ls1;
    __half* er0 = g_ench + ((size_t)(b * TT + gr0)) * 2048 + n * HDIM + lc;
    __half* er1 = g_ench + ((size_t)(b * TT + gr1)) * 2048 + n * HDIM + lc;
#pragma unroll
    for (int nt = 0; nt < 16; nt++) {
        *(__half2*)(er0 + nt * 8) = __floats2half2_rn(o[nt][0] * i0, o[nt][1] * i0);
        *(__half2*)(er1 + nt * 8) = __floats2half2_rn(o[nt][2] * i1, o[nt][3] * i1);
    }
}

// ---------------------------------------------------------------------------
extern "C" void kernel_launch(void* const* d_in, const int* in_sizes, int n_in,
                              void* d_out, int out_size)
{
    const float* x = (const float*)d_in[0];
    const int* positions = (const int*)d_in[1];
    // d_in[2] = attn_mask (causal) — analytic
    const float* w_q = (const float*)d_in[3];
    const float* w_kv = (const float*)d_in[4];
    const float* w_out = (const float*)d_in[5];
    float* out = (float*)d_out;

    float *qb, *kvb;
    __half *xh, *wth, *woth, *ench;
    cudaGetSymbolAddress((void**)&qb, g_q);
    cudaGetSymbolAddress((void**)&kvb, g_kv);
    cudaGetSymbolAddress((void**)&xh, g_xh);
    cudaGetSymbolAddress((void**)&wth, g_wth);
    cudaGetSymbolAddress((void**)&woth, g_woth);
    cudaGetSymbolAddress((void**)&ench, g_ench);

    TsTab tt;
    for (int i = 0; i < 64; i++) tt.ts[i] = pow(10000.0, -(double)i / 64.0);

    // prep: fp16 convert + transposed fp16 weights
    conv_half<<<(BB * TT * DD) / 1024, 256>>>(x, xh);
    transpose_half<<<dim3(4, 64, 16), dim3(32, 8)>>>(w_q, wth, 2048, 128);
    transpose_half<<<dim3(4, 64, 16), dim3(32, 8)>>>(
        w_kv, wth + (size_t)2048 * 2048, 2048, 128);
    transpose_half<<<dim3(64, 64, 1), dim3(32, 8)>>>(w_out, woth, 2048, 2048);
    rope_table<<<(BB * TT * 64) / 256, 256>>>(positions, tt);

    // merged QKV projection (fp16 mma)
    cudaFuncSetAttribute(gemm_h<0>, cudaFuncAttributeMaxDynamicSharedMemorySize,
                         HSMEM);
    cudaFuncSetAttribute(gemm_h<1>, cudaFuncAttributeMaxDynamicSharedMemorySize,
                         HSMEM);
    gemm_h<0><<<dim3(32, 32), 256, HSMEM>>>(xh, wth, nullptr);

    rope_apply<<<(BB * NHEADS * TT * 64) / 256, 256>>>(
        qb, NHEADS, NHEADS, 0.08838834764831845f);
    rope_apply<<<(BB * NKVH * TT * 64) / 256, 256>>>(
        kvb, NKVH, 16, 1.0f);

    cudaFuncSetAttribute(attn_kernel, cudaFuncAttributeMaxDynamicSharedMemorySize,
                         SMEM_ATTN);
    attn_kernel<<<dim3(TT / 64, NHEADS, BB), 128, SMEM_ATTN>>>();

    // output projection (fp16 mma)
    gemm_h<1><<<dim3(16, 32), 256, HSMEM>>>(ench, woth, out);
}